// round 9
// baseline (speedup 1.0000x reference)
#include <cuda_runtime.h>
#include <math.h>

// Problem constants
#define T_DIM   1024
#define B_DIM   8
#define INDIM   512
#define NOUT    192          // 64 v + 64 k + 64 alpha
#define M_TOT   (T_DIM*B_DIM)   // 8192 rows (t,b)
#define NCH     256          // chunks for log-cumsum (chunk = 4 t)
#define TCHK    4            // t per chunk
#define NSEG    8            // segments for the S scan
#define SEGT    128          // t per segment

#define LOG_EPS (-18.420680743952367f)   // logf(1e-8f)

// ---------------- device scratch (no allocations allowed) ----------------
__device__ float g_Wt[INDIM*NOUT];     // transposed+concatenated weights [k][n]
__device__ float g_bias[NOUT];
__device__ float g_v [M_TOT*64];
__device__ float g_k [M_TOT*64];
__device__ float g_la[M_TOT*64];       // log(max(sigmoid(a),eps))
__device__ float g_kd[M_TOT*64];       // k * decay
__device__ float g_carry[NCH*512];     // exclusive prefix of chunk sums
__device__ float g_inv[512];           // 1/(exp(total)+1e-8)
__device__ float g_P[(NSEG-1)*B_DIM*64*64];  // segment partial outer sums

// ---------------- K0: pack weights (transpose to [k][n]) + bias ----------------
__global__ void pack_weights(const float* __restrict__ Wv, const float* __restrict__ bv,
                             const float* __restrict__ Wk, const float* __restrict__ bk,
                             const float* __restrict__ Wa, const float* __restrict__ ba){
    int idx = blockIdx.x*256 + threadIdx.x;
    if (idx < NOUT*INDIM){
        int j = idx / INDIM;          // output col 0..191
        int k = idx - j*INDIM;        // k 0..511 (coalesced read)
        const float* W = (j < 64) ? Wv : ((j < 128) ? Wk : Wa);
        g_Wt[k*NOUT + j] = W[(j & 63)*INDIM + k];
    }
    if (idx < NOUT){
        g_bias[idx] = (idx < 64) ? bv[idx] : ((idx < 128) ? bk[idx-64] : ba[idx-128]);
    }
}

// ---------------- K1: projection GEMM (8192 x 512) x (512 x 192), scalar fmaf ----
// (R3's proven version: fastest measured proj.)
// Block: 256 threads; tile 64 rows x 192 cols. Thread: 4 rows x 12 cols.
__global__ void __launch_bounds__(256) proj_kernel(const float* __restrict__ x){
    __shared__ float sW[16*192];   // 12 KB  (k-tile x all 192 n)
    __shared__ float sX[16*64];    // 4 KB   (k-tile x 64 m, transposed)
    __shared__ float sB[192];

    int tid = threadIdx.x;
    int tx = tid & 15;             // n-group: 12 cols
    int ty = tid >> 4;             // m-group: 4 rows (0..15)
    if (tid < 192) sB[tid] = g_bias[tid];
    int mb = blockIdx.x * 64;

    float acc[4][12];
    #pragma unroll
    for (int i = 0; i < 4; i++)
        #pragma unroll
        for (int j = 0; j < 12; j++) acc[i][j] = 0.0f;

    for (int kk = 0; kk < INDIM; kk += 16){
        // W tile: 16*192 = 3072 floats = 768 float4 (3 per thread)
        {
            const float4* src = (const float4*)&g_Wt[kk*NOUT];
            float4* dst = (float4*)sW;
            dst[tid]       = src[tid];
            dst[tid + 256] = src[tid + 256];
            dst[tid + 512] = src[tid + 512];
        }
        // X tile, transposed: sX[k][m]; m = tid>>2 (0..63), kq = tid&3
        {
            int m  = tid >> 2;
            int kq = tid & 3;
            float4 xv = *(const float4*)&x[(mb + m)*INDIM + kk + kq*4];
            sX[(kq*4+0)*64 + m] = xv.x;
            sX[(kq*4+1)*64 + m] = xv.y;
            sX[(kq*4+2)*64 + m] = xv.z;
            sX[(kq*4+3)*64 + m] = xv.w;
        }
        __syncthreads();
        #pragma unroll
        for (int k = 0; k < 16; k++){
            float4 xr = *(float4*)&sX[k*64 + ty*4];
            float xm[4] = {xr.x, xr.y, xr.z, xr.w};
            float4 w0 = *(float4*)&sW[k*192 + tx*12 + 0];
            float4 w1 = *(float4*)&sW[k*192 + tx*12 + 4];
            float4 w2 = *(float4*)&sW[k*192 + tx*12 + 8];
            float wv[12] = {w0.x,w0.y,w0.z,w0.w, w1.x,w1.y,w1.z,w1.w, w2.x,w2.y,w2.z,w2.w};
            #pragma unroll
            for (int mi = 0; mi < 4; mi++)
                #pragma unroll
                for (int nj = 0; nj < 12; nj++)
                    acc[mi][nj] = fmaf(xm[mi], wv[nj], acc[mi][nj]);
        }
        __syncthreads();
    }

    // epilogue: bias + routing (v / k / fp32 stable log-sigmoid)
    #pragma unroll
    for (int mi = 0; mi < 4; mi++){
        int m = mb + ty*4 + mi;      // = t*8 + b
        #pragma unroll
        for (int nj = 0; nj < 12; nj++){
            int n = tx*12 + nj;
            float val = acc[mi][nj] + sB[n];
            if (n < 64){
                g_v[m*64 + n] = val;
            } else if (n < 128){
                g_k[m*64 + (n - 64)] = val;
            } else {
                // log(sigmoid(val)) = min(val,0) - log1p(exp(-|val|)), clamped
                float lsig = fminf(val, 0.0f) - log1pf(expf(-fabsf(val)));
                g_la[m*64 + (n - 128)] = fmaxf(lsig, LOG_EPS);
            }
        }
    }
}

// ---------------- K2: fused chunk sums + warp exclusive prefix ----------------
// 512 warps (grid 16 x 1024). Warp w handles bn = w. Lane handles chunk
// pass*32+lane: sums its TCHK la values (t-order preserved), warp-scans.
__global__ void __launch_bounds__(1024) chunk_scan(){
    int lane = threadIdx.x & 31;
    int bn   = (blockIdx.x * 1024 + threadIdx.x) >> 5;   // 0..511
    float carry = 0.0f;
    #pragma unroll
    for (int pass = 0; pass < NCH/32; pass++){
        int c = pass*32 + lane;
        const float* p = g_la + c*TCHK*512 + bn;
        float v = 0.0f;
        #pragma unroll
        for (int i = 0; i < TCHK; i++) v += p[i*512];
        // inclusive warp scan
        float s = v;
        #pragma unroll
        for (int off = 1; off < 32; off <<= 1){
            float t = __shfl_up_sync(0xffffffffu, s, off);
            if (lane >= off) s += t;
        }
        // exclusive = previous lane's inclusive (lane 0 -> 0)
        float ex = __shfl_up_sync(0xffffffffu, s, 1);
        if (lane == 0) ex = 0.0f;
        g_carry[c*512 + bn] = carry + ex;
        carry += __shfl_sync(0xffffffffu, s, 31);
    }
    if (lane == 31) g_inv[bn] = 1.0f / (expf(carry) + 1e-8f);  // ref underflow -> 1e-8
}

// ---------------- K3: decay + fold into k ----------------
__global__ void __launch_bounds__(512) decay_fold(){
    int c  = blockIdx.x;           // chunk 0..255
    int bn = threadIdx.x;
    float cum = g_carry[c*512 + bn];
    float inv = g_inv[bn];
    const float* lap = g_la + c*TCHK*512 + bn;
    const float* kp  = g_k  + c*TCHK*512 + bn;
    float*       kdp = g_kd + c*TCHK*512 + bn;
    #pragma unroll
    for (int i = 0; i < TCHK; i++){
        cum += lap[i*512];
        float dec = expf(cum) * inv;
        kdp[i*512] = kp[i*512] * dec;
    }
}

// ---------------- K4: segment partial outer sums ----------------
// grid (16 dq, 8 b, NSEG-1 seg), block 64 = (dg 0..3) x (nq 0..15)
__global__ void __launch_bounds__(64) seg_partial(){
    int dq = blockIdx.x, b = blockIdx.y, seg = blockIdx.z;
    __shared__ float s_v[SEGT*4];
    int tid = threadIdx.x;
    for (int i = tid; i < SEGT; i += 64){
        float4 vv = *(const float4*)&g_v[(seg*SEGT + i)*512 + b*64 + dq*4];
        *(float4*)&s_v[i*4] = vv;
    }
    __syncthreads();
    int dg = tid >> 4, nq = tid & 15;
    int d = dq*4 + dg;
    float4 acc = make_float4(0.f, 0.f, 0.f, 0.f);
    const float* kdp = g_kd + seg*SEGT*512 + b*64 + nq*4;
    #pragma unroll 8
    for (int t = 0; t < SEGT; t++){
        float4 kd = *(const float4*)(kdp + t*512);
        float vv = s_v[t*4 + dg];
        acc.x = fmaf(vv, kd.x, acc.x);
        acc.y = fmaf(vv, kd.y, acc.y);
        acc.z = fmaf(vv, kd.z, acc.z);
        acc.w = fmaf(vv, kd.w, acc.w);
    }
    *(float4*)&g_P[(seg*B_DIM + b)*4096 + d*64 + nq*4] = acc;
}

// ---------------- K5: segmented scan + store (128 MB) ----------------
// grid (16 dq, 8 b, NSEG seg), block 64 = (dg 0..3) x (nq 0..15)
__global__ void __launch_bounds__(64) scan_kernel(float* __restrict__ out){
    int dq = blockIdx.x, b = blockIdx.y, seg = blockIdx.z;
    __shared__ float s_v[SEGT*4];
    int tid = threadIdx.x;
    for (int i = tid; i < SEGT; i += 64){
        float4 vv = *(const float4*)&g_v[(seg*SEGT + i)*512 + b*64 + dq*4];
        *(float4*)&s_v[i*4] = vv;
    }
    __syncthreads();
    int dg = tid >> 4, nq = tid & 15;
    int d = dq*4 + dg;
    float4 acc = make_float4(0.f, 0.f, 0.f, 0.f);
    for (int s = 0; s < seg; s++){
        float4 pv = *(const float4*)&g_P[(s*B_DIM + b)*4096 + d*64 + nq*4];
        acc.x += pv.x; acc.y += pv.y; acc.z += pv.z; acc.w += pv.w;
    }
    const float* kdp = g_kd + seg*SEGT*512 + b*64 + nq*4;
    float* outp = out + (size_t)(seg*SEGT)*32768 + b*4096 + d*64 + nq*4;
    #pragma unroll 8
    for (int t = 0; t < SEGT; t++){
        float4 kd = *(const float4*)(kdp + t*512);
        float vv = s_v[t*4 + dg];
        acc.x = fmaf(vv, kd.x, acc.x);
        acc.y = fmaf(vv, kd.y, acc.y);
        acc.z = fmaf(vv, kd.z, acc.z);
        acc.w = fmaf(vv, kd.w, acc.w);
        *(float4*)(outp + (size_t)t*32768) = acc;
    }
}

// ---------------- launch ----------------
extern "C" void kernel_launch(void* const* d_in, const int* in_sizes, int n_in,
                              void* d_out, int out_size){
    const float* x  = (const float*)d_in[0];
    const float* Wv = (const float*)d_in[1];
    const float* bv = (const float*)d_in[2];
    const float* Wk = (const float*)d_in[3];
    const float* bk = (const float*)d_in[4];
    const float* Wa = (const float*)d_in[5];
    const float* ba = (const float*)d_in[6];
    float* out = (float*)d_out;

    pack_weights<<<(NOUT*INDIM + 255)/256, 256>>>(Wv, bv, Wk, bk, Wa, ba);
    proj_kernel<<<M_TOT/64, 256>>>(x);
    chunk_scan<<<16, 1024>>>();
    decay_fold<<<NCH, 512>>>();
    dim3 g4(16, B_DIM, NSEG-1);
    seg_partial<<<g4, 64>>>();
    dim3 g5(16, B_DIM, NSEG);
    scan_kernel<<<g5, 64>>>(out);
}

// round 10
// speedup vs baseline: 1.4764x; 1.4764x over previous
#include <cuda_runtime.h>
#include <math.h>

// Problem constants
#define T_DIM   1024
#define B_DIM   8
#define INDIM   512
#define NOUT    192          // 64 v + 64 k + 64 alpha
#define M_TOT   (T_DIM*B_DIM)   // 8192 rows (t,b)
#define NCH     128          // chunks for log-cumsum (chunk = 8 t)
#define TCHK    8            // t per chunk
#define NSEG    32           // segments for the S scan
#define SEGT    32           // t per segment

#define LOG_EPS (-18.420680743952367f)   // logf(1e-8f)

// ---------------- device scratch (no allocations allowed) ----------------
__device__ float g_Wt[INDIM*NOUT];     // transposed+concatenated weights [k][n]
__device__ float g_bias[NOUT];
__device__ float g_v [M_TOT*64];       // (t*8+b)*64 + d
__device__ float g_k [M_TOT*64];
__device__ float g_la[M_TOT*64];       // log(max(sigmoid(a),eps))
__device__ float g_kd[M_TOT*64];       // k * decay
__device__ float g_csum[NCH*512];      // per-chunk log sums
__device__ float g_carry[NCH*512];     // exclusive prefix of chunk sums
__device__ float g_inv[512];           // 1/(exp(total)+1e-8)
__device__ float g_P[NSEG*B_DIM*64*64];  // segment sums -> exclusive prefix (4 MB)

// ---------------- K0: pack weights (transpose to [k][n]) + bias ----------------
__global__ void pack_weights(const float* __restrict__ Wv, const float* __restrict__ bv,
                             const float* __restrict__ Wk, const float* __restrict__ bk,
                             const float* __restrict__ Wa, const float* __restrict__ ba){
    int idx = blockIdx.x*256 + threadIdx.x;
    if (idx < NOUT*INDIM){
        int j = idx / INDIM;          // output col 0..191
        int k = idx - j*INDIM;        // k 0..511 (coalesced read)
        const float* W = (j < 64) ? Wv : ((j < 128) ? Wk : Wa);
        g_Wt[k*NOUT + j] = W[(j & 63)*INDIM + k];
    }
    if (idx < NOUT){
        g_bias[idx] = (idx < 64) ? bv[idx] : ((idx < 128) ? bk[idx-64] : ba[idx-128]);
    }
}

// ---------------- K1: projection GEMM (R3 scalar fmaf, measured-best) ----------
__global__ void __launch_bounds__(256) proj_kernel(const float* __restrict__ x){
    __shared__ float sW[16*192];
    __shared__ float sX[16*64];
    __shared__ float sB[192];

    int tid = threadIdx.x;
    int tx = tid & 15;
    int ty = tid >> 4;
    if (tid < 192) sB[tid] = g_bias[tid];
    int mb = blockIdx.x * 64;

    float acc[4][12];
    #pragma unroll
    for (int i = 0; i < 4; i++)
        #pragma unroll
        for (int j = 0; j < 12; j++) acc[i][j] = 0.0f;

    for (int kk = 0; kk < INDIM; kk += 16){
        {
            const float4* src = (const float4*)&g_Wt[kk*NOUT];
            float4* dst = (float4*)sW;
            dst[tid]       = src[tid];
            dst[tid + 256] = src[tid + 256];
            dst[tid + 512] = src[tid + 512];
        }
        {
            int m  = tid >> 2;
            int kq = tid & 3;
            float4 xv = *(const float4*)&x[(mb + m)*INDIM + kk + kq*4];
            sX[(kq*4+0)*64 + m] = xv.x;
            sX[(kq*4+1)*64 + m] = xv.y;
            sX[(kq*4+2)*64 + m] = xv.z;
            sX[(kq*4+3)*64 + m] = xv.w;
        }
        __syncthreads();
        #pragma unroll
        for (int k = 0; k < 16; k++){
            float4 xr = *(float4*)&sX[k*64 + ty*4];
            float xm[4] = {xr.x, xr.y, xr.z, xr.w};
            float4 w0 = *(float4*)&sW[k*192 + tx*12 + 0];
            float4 w1 = *(float4*)&sW[k*192 + tx*12 + 4];
            float4 w2 = *(float4*)&sW[k*192 + tx*12 + 8];
            float wv[12] = {w0.x,w0.y,w0.z,w0.w, w1.x,w1.y,w1.z,w1.w, w2.x,w2.y,w2.z,w2.w};
            #pragma unroll
            for (int mi = 0; mi < 4; mi++)
                #pragma unroll
                for (int nj = 0; nj < 12; nj++)
                    acc[mi][nj] = fmaf(xm[mi], wv[nj], acc[mi][nj]);
        }
        __syncthreads();
    }

    #pragma unroll
    for (int mi = 0; mi < 4; mi++){
        int m = mb + ty*4 + mi;
        #pragma unroll
        for (int nj = 0; nj < 12; nj++){
            int n = tx*12 + nj;
            float val = acc[mi][nj] + sB[n];
            if (n < 64){
                g_v[m*64 + n] = val;
            } else if (n < 128){
                g_k[m*64 + (n - 64)] = val;
            } else {
                float lsig = fminf(val, 0.0f) - log1pf(expf(-fabsf(val)));
                g_la[m*64 + (n - 128)] = fmaxf(lsig, LOG_EPS);
            }
        }
    }
}

// ---------------- K2a: per-chunk log sums (coalesced, R3) ----------------
__global__ void __launch_bounds__(512) chunk_logsum(){
    int c  = blockIdx.x;           // chunk 0..127
    int bn = threadIdx.x;
    const float* p = g_la + c*TCHK*512 + bn;
    float s = 0.0f;
    #pragma unroll
    for (int i = 0; i < TCHK; i++) s += p[i*512];
    g_csum[c*512 + bn] = s;
}

// ---------------- K2b: warp-per-bn exclusive prefix over chunks (R5) ----------
__global__ void __launch_bounds__(1024) carry_prefix(){
    int lane = threadIdx.x & 31;
    int bn   = (blockIdx.x * 1024 + threadIdx.x) >> 5;   // 0..511
    float carry = 0.0f;
    #pragma unroll
    for (int pass = 0; pass < NCH/32; pass++){
        int c = pass*32 + lane;
        float v = g_csum[c*512 + bn];
        float s = v;
        #pragma unroll
        for (int off = 1; off < 32; off <<= 1){
            float t = __shfl_up_sync(0xffffffffu, s, off);
            if (lane >= off) s += t;
        }
        float ex = __shfl_up_sync(0xffffffffu, s, 1);
        if (lane == 0) ex = 0.0f;
        g_carry[c*512 + bn] = carry + ex;
        carry += __shfl_sync(0xffffffffu, s, 31);
    }
    if (lane == 31) g_inv[bn] = 1.0f / (expf(carry) + 1e-8f);
}

// ---------------- K3: decay + fold into k ----------------
__global__ void __launch_bounds__(512) decay_fold(){
    int c  = blockIdx.x;           // chunk 0..127
    int bn = threadIdx.x;
    float cum = g_carry[c*512 + bn];
    float inv = g_inv[bn];
    const float* lap = g_la + c*TCHK*512 + bn;
    const float* kp  = g_k  + c*TCHK*512 + bn;
    float*       kdp = g_kd + c*TCHK*512 + bn;
    #pragma unroll
    for (int i = 0; i < TCHK; i++){
        cum += lap[i*512];
        float dec = expf(cum) * inv;
        kdp[i*512] = kp[i*512] * dec;
    }
}

// ---------------- K4: per-segment outer-product sums (kd read ONCE) ----------
// grid (NSEG, B_DIM), 256 threads. Thread (dq=tid>>4, n4=tid&15):
// d = dq*4..dq*4+3, n = n4*4..n4*4+3 -> 4 float4 accumulators.
__global__ void __launch_bounds__(256) seg_sums(){
    int seg = blockIdx.x, b = blockIdx.y;
    __shared__ float s_v[SEGT*64];
    __shared__ float s_kd[SEGT*64];
    int tid = threadIdx.x;
    for (int i = tid; i < SEGT*16; i += 256){
        int t = i >> 4, q = i & 15;
        int row = ((seg*SEGT + t)*B_DIM + b)*64;
        ((float4*)s_v)[i]  = *(const float4*)&g_v [row + q*4];
        ((float4*)s_kd)[i] = *(const float4*)&g_kd[row + q*4];
    }
    __syncthreads();
    int dq = tid >> 4, n4 = tid & 15;
    float4 a0 = {0,0,0,0}, a1 = {0,0,0,0}, a2 = {0,0,0,0}, a3 = {0,0,0,0};
    #pragma unroll 4
    for (int t = 0; t < SEGT; t++){
        float4 kd = *(const float4*)&s_kd[t*64 + n4*4];
        float4 vv = *(const float4*)&s_v [t*64 + dq*4];
        a0.x = fmaf(vv.x, kd.x, a0.x); a0.y = fmaf(vv.x, kd.y, a0.y);
        a0.z = fmaf(vv.x, kd.z, a0.z); a0.w = fmaf(vv.x, kd.w, a0.w);
        a1.x = fmaf(vv.y, kd.x, a1.x); a1.y = fmaf(vv.y, kd.y, a1.y);
        a1.z = fmaf(vv.y, kd.z, a1.z); a1.w = fmaf(vv.y, kd.w, a1.w);
        a2.x = fmaf(vv.z, kd.x, a2.x); a2.y = fmaf(vv.z, kd.y, a2.y);
        a2.z = fmaf(vv.z, kd.z, a2.z); a2.w = fmaf(vv.z, kd.w, a2.w);
        a3.x = fmaf(vv.w, kd.x, a3.x); a3.y = fmaf(vv.w, kd.y, a3.y);
        a3.z = fmaf(vv.w, kd.z, a3.z); a3.w = fmaf(vv.w, kd.w, a3.w);
    }
    float* P = g_P + (seg*B_DIM + b)*4096;
    *(float4*)&P[(dq*4+0)*64 + n4*4] = a0;
    *(float4*)&P[(dq*4+1)*64 + n4*4] = a1;
    *(float4*)&P[(dq*4+2)*64 + n4*4] = a2;
    *(float4*)&P[(dq*4+3)*64 + n4*4] = a3;
}

// ---------------- K4b: in-place exclusive prefix of P along seg ---------------
// 32768 items (b*4096+i); each thread scans 32 segments in order.
__global__ void __launch_bounds__(256) seg_prefix(){
    int idx = blockIdx.x*256 + threadIdx.x;   // 0..32767
    float carry = 0.0f;
    #pragma unroll 8
    for (int s = 0; s < NSEG; s++){
        float v = g_P[s*32768 + idx];
        g_P[s*32768 + idx] = carry;
        carry += v;
    }
}

// ---------------- K5: scan + store (128 MB), kd read ONCE ---------------------
// grid (NSEG, B_DIM), 256 threads; same thread map as seg_sums.
__global__ void __launch_bounds__(256) scan_kernel(float* __restrict__ out){
    int seg = blockIdx.x, b = blockIdx.y;
    __shared__ float s_v[SEGT*64];
    __shared__ float s_kd[SEGT*64];
    int tid = threadIdx.x;
    for (int i = tid; i < SEGT*16; i += 256){
        int t = i >> 4, q = i & 15;
        int row = ((seg*SEGT + t)*B_DIM + b)*64;
        ((float4*)s_v)[i]  = *(const float4*)&g_v [row + q*4];
        ((float4*)s_kd)[i] = *(const float4*)&g_kd[row + q*4];
    }
    __syncthreads();
    int dq = tid >> 4, n4 = tid & 15;
    const float* P = g_P + (seg*B_DIM + b)*4096;
    float4 a0 = *(const float4*)&P[(dq*4+0)*64 + n4*4];
    float4 a1 = *(const float4*)&P[(dq*4+1)*64 + n4*4];
    float4 a2 = *(const float4*)&P[(dq*4+2)*64 + n4*4];
    float4 a3 = *(const float4*)&P[(dq*4+3)*64 + n4*4];
    #pragma unroll 4
    for (int t = 0; t < SEGT; t++){
        float4 kd = *(const float4*)&s_kd[t*64 + n4*4];
        float4 vv = *(const float4*)&s_v [t*64 + dq*4];
        a0.x = fmaf(vv.x, kd.x, a0.x); a0.y = fmaf(vv.x, kd.y, a0.y);
        a0.z = fmaf(vv.x, kd.z, a0.z); a0.w = fmaf(vv.x, kd.w, a0.w);
        a1.x = fmaf(vv.y, kd.x, a1.x); a1.y = fmaf(vv.y, kd.y, a1.y);
        a1.z = fmaf(vv.y, kd.z, a1.z); a1.w = fmaf(vv.y, kd.w, a1.w);
        a2.x = fmaf(vv.z, kd.x, a2.x); a2.y = fmaf(vv.z, kd.y, a2.y);
        a2.z = fmaf(vv.z, kd.z, a2.z); a2.w = fmaf(vv.z, kd.w, a2.w);
        a3.x = fmaf(vv.w, kd.x, a3.x); a3.y = fmaf(vv.w, kd.y, a3.y);
        a3.z = fmaf(vv.w, kd.z, a3.z); a3.w = fmaf(vv.w, kd.w, a3.w);
        float* orow = out + (size_t)((seg*SEGT + t)*B_DIM + b)*4096;
        *(float4*)&orow[(dq*4+0)*64 + n4*4] = a0;
        *(float4*)&orow[(dq*4+1)*64 + n4*4] = a1;
        *(float4*)&orow[(dq*4+2)*64 + n4*4] = a2;
        *(float4*)&orow[(dq*4+3)*64 + n4*4] = a3;
    }
}

// ---------------- launch ----------------
extern "C" void kernel_launch(void* const* d_in, const int* in_sizes, int n_in,
                              void* d_out, int out_size){
    const float* x  = (const float*)d_in[0];
    const float* Wv = (const float*)d_in[1];
    const float* bv = (const float*)d_in[2];
    const float* Wk = (const float*)d_in[3];
    const float* bk = (const float*)d_in[4];
    const float* Wa = (const float*)d_in[5];
    const float* ba = (const float*)d_in[6];
    float* out = (float*)d_out;

    pack_weights<<<(NOUT*INDIM + 255)/256, 256>>>(Wv, bv, Wk, bk, Wa, ba);
    proj_kernel<<<M_TOT/64, 256>>>(x);
    chunk_logsum<<<NCH, 512>>>();
    carry_prefix<<<16, 1024>>>();
    decay_fold<<<NCH, 512>>>();
    dim3 gseg(NSEG, B_DIM);
    seg_sums<<<gseg, 256>>>();
    seg_prefix<<<128, 256>>>();
    scan_kernel<<<gseg, 256>>>(out);
}

// round 11
// speedup vs baseline: 1.5307x; 1.0368x over previous
#include <cuda_runtime.h>
#include <math.h>

// Problem constants
#define T_DIM   1024
#define B_DIM   8
#define INDIM   512
#define NOUT    192          // 64 v + 64 k + 64 alpha
#define M_TOT   (T_DIM*B_DIM)   // 8192 rows (t,b)
#define NCH     128          // chunks for log-cumsum (chunk = 8 t)
#define TCHK    8            // t per chunk
#define NSEG    32           // segments for the S scan
#define SEGT    32           // t per segment

#define LOG_EPS (-18.420680743952367f)   // logf(1e-8f)

// ---------------- device scratch (no allocations allowed) ----------------
__device__ float g_Wt[INDIM*NOUT];     // transposed+concatenated weights [k][n]
__device__ float g_bias[NOUT];
__device__ float g_v [M_TOT*64];       // (t*8+b)*64 + d
__device__ float g_k [M_TOT*64];
__device__ float g_la[M_TOT*64];       // log(max(sigmoid(a),eps))
__device__ float g_kd[M_TOT*64];       // k * decay
__device__ float g_carry[NCH*512];     // exclusive prefix of chunk sums
__device__ float g_inv[512];           // 1/(exp(total)+1e-8)
__device__ float g_P[NSEG*B_DIM*64*64];  // segment sums -> exclusive prefix (4 MB)

// ---------------- K0: pack weights (transpose to [k][n]) + bias ----------------
__global__ void pack_weights(const float* __restrict__ Wv, const float* __restrict__ bv,
                             const float* __restrict__ Wk, const float* __restrict__ bk,
                             const float* __restrict__ Wa, const float* __restrict__ ba){
    int idx = blockIdx.x*256 + threadIdx.x;
    if (idx < NOUT*INDIM){
        int j = idx / INDIM;          // output col 0..191
        int k = idx - j*INDIM;        // k 0..511 (coalesced read)
        const float* W = (j < 64) ? Wv : ((j < 128) ? Wk : Wa);
        g_Wt[k*NOUT + j] = W[(j & 63)*INDIM + k];
    }
    if (idx < NOUT){
        g_bias[idx] = (idx < 64) ? bv[idx] : ((idx < 128) ? bk[idx-64] : ba[idx-128]);
    }
}

// ---------------- K1: projection GEMM (R3 scalar fmaf, measured-best) ----------
__global__ void __launch_bounds__(256) proj_kernel(const float* __restrict__ x){
    __shared__ float sW[16*192];
    __shared__ float sX[16*64];
    __shared__ float sB[192];

    int tid = threadIdx.x;
    int tx = tid & 15;
    int ty = tid >> 4;
    if (tid < 192) sB[tid] = g_bias[tid];
    int mb = blockIdx.x * 64;

    float acc[4][12];
    #pragma unroll
    for (int i = 0; i < 4; i++)
        #pragma unroll
        for (int j = 0; j < 12; j++) acc[i][j] = 0.0f;

    for (int kk = 0; kk < INDIM; kk += 16){
        {
            const float4* src = (const float4*)&g_Wt[kk*NOUT];
            float4* dst = (float4*)sW;
            dst[tid]       = src[tid];
            dst[tid + 256] = src[tid + 256];
            dst[tid + 512] = src[tid + 512];
        }
        {
            int m  = tid >> 2;
            int kq = tid & 3;
            float4 xv = *(const float4*)&x[(mb + m)*INDIM + kk + kq*4];
            sX[(kq*4+0)*64 + m] = xv.x;
            sX[(kq*4+1)*64 + m] = xv.y;
            sX[(kq*4+2)*64 + m] = xv.z;
            sX[(kq*4+3)*64 + m] = xv.w;
        }
        __syncthreads();
        #pragma unroll
        for (int k = 0; k < 16; k++){
            float4 xr = *(float4*)&sX[k*64 + ty*4];
            float xm[4] = {xr.x, xr.y, xr.z, xr.w};
            float4 w0 = *(float4*)&sW[k*192 + tx*12 + 0];
            float4 w1 = *(float4*)&sW[k*192 + tx*12 + 4];
            float4 w2 = *(float4*)&sW[k*192 + tx*12 + 8];
            float wv[12] = {w0.x,w0.y,w0.z,w0.w, w1.x,w1.y,w1.z,w1.w, w2.x,w2.y,w2.z,w2.w};
            #pragma unroll
            for (int mi = 0; mi < 4; mi++)
                #pragma unroll
                for (int nj = 0; nj < 12; nj++)
                    acc[mi][nj] = fmaf(xm[mi], wv[nj], acc[mi][nj]);
        }
        __syncthreads();
    }

    #pragma unroll
    for (int mi = 0; mi < 4; mi++){
        int m = mb + ty*4 + mi;
        #pragma unroll
        for (int nj = 0; nj < 12; nj++){
            int n = tx*12 + nj;
            float val = acc[mi][nj] + sB[n];
            if (n < 64){
                g_v[m*64 + n] = val;
            } else if (n < 128){
                g_k[m*64 + (n - 64)] = val;
            } else {
                float lsig = fminf(val, 0.0f) - log1pf(expf(-fabsf(val)));
                g_la[m*64 + (n - 128)] = fmaxf(lsig, LOG_EPS);
            }
        }
    }
}

// ---------------- K2: fused chunk sums + exclusive prefix (coalesced) ---------
// 16 blocks x 1024 threads; block handles 32 bn. Per pass: load 32c x 32bn tile
// of chunk sums coalesced along bn, smem-transpose, warp-scan per bn, transpose
// back, write g_carry coalesced. Same summation order as before.
__global__ void __launch_bounds__(1024) la_scan(){
    __shared__ float tile[32][33];
    int lane = threadIdx.x & 31;
    int wid  = threadIdx.x >> 5;          // 0..31
    int bnBase = blockIdx.x * 32;
    int myBn = bnBase + wid;
    float carry = 0.0f;
    #pragma unroll
    for (int pass = 0; pass < NCH/32; pass++){
        // chunk sum: c = pass*32 + wid, bn = bnBase + lane (coalesced)
        int c = pass*32 + wid;
        const float* p = g_la + c*TCHK*512 + bnBase + lane;
        float s = 0.0f;
        #pragma unroll
        for (int i = 0; i < TCHK; i++) s += p[i*512];
        tile[wid][lane] = s;
        __syncthreads();
        // warp 'wid' scans chunks for bn = myBn: chunk index = lane
        float v = tile[lane][wid];
        float sc = v;
        #pragma unroll
        for (int off = 1; off < 32; off <<= 1){
            float t = __shfl_up_sync(0xffffffffu, sc, off);
            if (lane >= off) sc += t;
        }
        float ex = __shfl_up_sync(0xffffffffu, sc, 1);
        if (lane == 0) ex = 0.0f;
        float tot = __shfl_sync(0xffffffffu, sc, 31);
        __syncthreads();                  // tile reuse
        tile[lane][wid] = carry + ex;     // [chunk][bn]
        carry += tot;
        __syncthreads();
        // coalesced write: thread (wid,lane) -> chunk pass*32+wid, bn bnBase+lane
        g_carry[(pass*32 + wid)*512 + bnBase + lane] = tile[wid][lane];
        __syncthreads();
    }
    if (lane == 31) g_inv[myBn] = 1.0f / (expf(carry) + 1e-8f);  // ref underflow -> 1e-8
}

// ---------------- K3: decay + fold into k ----------------
__global__ void __launch_bounds__(512) decay_fold(){
    int c  = blockIdx.x;           // chunk 0..127
    int bn = threadIdx.x;
    float cum = g_carry[c*512 + bn];
    float inv = g_inv[bn];
    const float* lap = g_la + c*TCHK*512 + bn;
    const float* kp  = g_k  + c*TCHK*512 + bn;
    float*       kdp = g_kd + c*TCHK*512 + bn;
    #pragma unroll
    for (int i = 0; i < TCHK; i++){
        cum += lap[i*512];
        float dec = expf(cum) * inv;
        kdp[i*512] = kp[i*512] * dec;
    }
}

// ---------------- K4: per-segment outer-product sums (kd read ONCE) ----------
__global__ void __launch_bounds__(256) seg_sums(){
    int seg = blockIdx.x, b = blockIdx.y;
    __shared__ float s_v[SEGT*64];
    __shared__ float s_kd[SEGT*64];
    int tid = threadIdx.x;
    for (int i = tid; i < SEGT*16; i += 256){
        int t = i >> 4, q = i & 15;
        int row = ((seg*SEGT + t)*B_DIM + b)*64;
        ((float4*)s_v)[i]  = *(const float4*)&g_v [row + q*4];
        ((float4*)s_kd)[i] = *(const float4*)&g_kd[row + q*4];
    }
    __syncthreads();
    int dq = tid >> 4, n4 = tid & 15;
    float4 a0 = {0,0,0,0}, a1 = {0,0,0,0}, a2 = {0,0,0,0}, a3 = {0,0,0,0};
    #pragma unroll 4
    for (int t = 0; t < SEGT; t++){
        float4 kd = *(const float4*)&s_kd[t*64 + n4*4];
        float4 vv = *(const float4*)&s_v [t*64 + dq*4];
        a0.x = fmaf(vv.x, kd.x, a0.x); a0.y = fmaf(vv.x, kd.y, a0.y);
        a0.z = fmaf(vv.x, kd.z, a0.z); a0.w = fmaf(vv.x, kd.w, a0.w);
        a1.x = fmaf(vv.y, kd.x, a1.x); a1.y = fmaf(vv.y, kd.y, a1.y);
        a1.z = fmaf(vv.y, kd.z, a1.z); a1.w = fmaf(vv.y, kd.w, a1.w);
        a2.x = fmaf(vv.z, kd.x, a2.x); a2.y = fmaf(vv.z, kd.y, a2.y);
        a2.z = fmaf(vv.z, kd.z, a2.z); a2.w = fmaf(vv.z, kd.w, a2.w);
        a3.x = fmaf(vv.w, kd.x, a3.x); a3.y = fmaf(vv.w, kd.y, a3.y);
        a3.z = fmaf(vv.w, kd.z, a3.z); a3.w = fmaf(vv.w, kd.w, a3.w);
    }
    float* P = g_P + (seg*B_DIM + b)*4096;
    *(float4*)&P[(dq*4+0)*64 + n4*4] = a0;
    *(float4*)&P[(dq*4+1)*64 + n4*4] = a1;
    *(float4*)&P[(dq*4+2)*64 + n4*4] = a2;
    *(float4*)&P[(dq*4+3)*64 + n4*4] = a3;
}

// ---------------- K4b: in-place exclusive prefix of P along seg ---------------
__global__ void __launch_bounds__(256) seg_prefix(){
    int idx = blockIdx.x*256 + threadIdx.x;   // 0..32767
    float carry = 0.0f;
    #pragma unroll 8
    for (int s = 0; s < NSEG; s++){
        float v = g_P[s*32768 + idx];
        g_P[s*32768 + idx] = carry;
        carry += v;
    }
}

// ---------------- K5: scan + store (128 MB), kd read ONCE ---------------------
__global__ void __launch_bounds__(256) scan_kernel(float* __restrict__ out){
    int seg = blockIdx.x, b = blockIdx.y;
    __shared__ float s_v[SEGT*64];
    __shared__ float s_kd[SEGT*64];
    int tid = threadIdx.x;
    for (int i = tid; i < SEGT*16; i += 256){
        int t = i >> 4, q = i & 15;
        int row = ((seg*SEGT + t)*B_DIM + b)*64;
        ((float4*)s_v)[i]  = *(const float4*)&g_v [row + q*4];
        ((float4*)s_kd)[i] = *(const float4*)&g_kd[row + q*4];
    }
    __syncthreads();
    int dq = tid >> 4, n4 = tid & 15;
    const float* P = g_P + (seg*B_DIM + b)*4096;
    float4 a0 = *(const float4*)&P[(dq*4+0)*64 + n4*4];
    float4 a1 = *(const float4*)&P[(dq*4+1)*64 + n4*4];
    float4 a2 = *(const float4*)&P[(dq*4+2)*64 + n4*4];
    float4 a3 = *(const float4*)&P[(dq*4+3)*64 + n4*4];
    #pragma unroll 4
    for (int t = 0; t < SEGT; t++){
        float4 kd = *(const float4*)&s_kd[t*64 + n4*4];
        float4 vv = *(const float4*)&s_v [t*64 + dq*4];
        a0.x = fmaf(vv.x, kd.x, a0.x); a0.y = fmaf(vv.x, kd.y, a0.y);
        a0.z = fmaf(vv.x, kd.z, a0.z); a0.w = fmaf(vv.x, kd.w, a0.w);
        a1.x = fmaf(vv.y, kd.x, a1.x); a1.y = fmaf(vv.y, kd.y, a1.y);
        a1.z = fmaf(vv.y, kd.z, a1.z); a1.w = fmaf(vv.y, kd.w, a1.w);
        a2.x = fmaf(vv.z, kd.x, a2.x); a2.y = fmaf(vv.z, kd.y, a2.y);
        a2.z = fmaf(vv.z, kd.z, a2.z); a2.w = fmaf(vv.z, kd.w, a2.w);
        a3.x = fmaf(vv.w, kd.x, a3.x); a3.y = fmaf(vv.w, kd.y, a3.y);
        a3.z = fmaf(vv.w, kd.z, a3.z); a3.w = fmaf(vv.w, kd.w, a3.w);
        float* orow = out + (size_t)((seg*SEGT + t)*B_DIM + b)*4096;
        *(float4*)&orow[(dq*4+0)*64 + n4*4] = a0;
        *(float4*)&orow[(dq*4+1)*64 + n4*4] = a1;
        *(float4*)&orow[(dq*4+2)*64 + n4*4] = a2;
        *(float4*)&orow[(dq*4+3)*64 + n4*4] = a3;
    }
}

// ---------------- launch ----------------
extern "C" void kernel_launch(void* const* d_in, const int* in_sizes, int n_in,
                              void* d_out, int out_size){
    const float* x  = (const float*)d_in[0];
    const float* Wv = (const float*)d_in[1];
    const float* bv = (const float*)d_in[2];
    const float* Wk = (const float*)d_in[3];
    const float* bk = (const float*)d_in[4];
    const float* Wa = (const float*)d_in[5];
    const float* ba = (const float*)d_in[6];
    float* out = (float*)d_out;

    pack_weights<<<(NOUT*INDIM + 255)/256, 256>>>(Wv, bv, Wk, bk, Wa, ba);
    proj_kernel<<<M_TOT/64, 256>>>(x);
    la_scan<<<16, 1024>>>();
    decay_fold<<<NCH, 512>>>();
    dim3 gseg(NSEG, B_DIM);
    seg_sums<<<gseg, 256>>>();
    seg_prefix<<<128, 256>>>();
    scan_kernel<<<gseg, 256>>>(out);
}

// round 12
// speedup vs baseline: 1.5930x; 1.0407x over previous
#include <cuda_runtime.h>
#include <math.h>

// Problem constants
#define T_DIM   1024
#define B_DIM   8
#define INDIM   512
#define NOUT    192          // 64 v + 64 k + 64 alpha
#define M_TOT   (T_DIM*B_DIM)   // 8192 rows (t,b)
#define NCH     128          // chunks for log-cumsum (chunk = 8 t)
#define TCHK    8            // t per chunk
#define NSEG    32           // segments for the S scan
#define SEGT    32           // t per segment (= 4 chunks)

#define LOG_EPS (-18.420680743952367f)   // logf(1e-8f)

// ---------------- device scratch (no allocations allowed) ----------------
__device__ float g_Wt[INDIM*NOUT];     // transposed+concatenated weights [k][n]
__device__ float g_bias[NOUT];
__device__ float g_v [M_TOT*64];       // (t*8+b)*64 + d
__device__ float g_k [M_TOT*64];
__device__ float g_la[M_TOT*64];       // log(max(sigmoid(a),eps))
__device__ float g_carry[NCH*512];     // exclusive prefix of chunk sums
__device__ float g_inv[512];           // 1/(exp(total)+1e-8)
__device__ float g_P[NSEG*B_DIM*64*64];  // segment sums -> exclusive prefix (4 MB)

// ---------------- K0: pack weights (transpose to [k][n]) + bias ----------------
__global__ void pack_weights(const float* __restrict__ Wv, const float* __restrict__ bv,
                             const float* __restrict__ Wk, const float* __restrict__ bk,
                             const float* __restrict__ Wa, const float* __restrict__ ba){
    int idx = blockIdx.x*256 + threadIdx.x;
    if (idx < NOUT*INDIM){
        int j = idx / INDIM;          // output col 0..191
        int k = idx - j*INDIM;        // k 0..511 (coalesced read)
        const float* W = (j < 64) ? Wv : ((j < 128) ? Wk : Wa);
        g_Wt[k*NOUT + j] = W[(j & 63)*INDIM + k];
    }
    if (idx < NOUT){
        g_bias[idx] = (idx < 64) ? bv[idx] : ((idx < 128) ? bk[idx-64] : ba[idx-128]);
    }
}

// ---------------- K1: projection GEMM (R3 scalar fmaf, measured-best) ----------
__global__ void __launch_bounds__(256) proj_kernel(const float* __restrict__ x){
    __shared__ float sW[16*192];
    __shared__ float sX[16*64];
    __shared__ float sB[192];

    int tid = threadIdx.x;
    int tx = tid & 15;
    int ty = tid >> 4;
    if (tid < 192) sB[tid] = g_bias[tid];
    int mb = blockIdx.x * 64;

    float acc[4][12];
    #pragma unroll
    for (int i = 0; i < 4; i++)
        #pragma unroll
        for (int j = 0; j < 12; j++) acc[i][j] = 0.0f;

    for (int kk = 0; kk < INDIM; kk += 16){
        {
            const float4* src = (const float4*)&g_Wt[kk*NOUT];
            float4* dst = (float4*)sW;
            dst[tid]       = src[tid];
            dst[tid + 256] = src[tid + 256];
            dst[tid + 512] = src[tid + 512];
        }
        {
            int m  = tid >> 2;
            int kq = tid & 3;
            float4 xv = *(const float4*)&x[(mb + m)*INDIM + kk + kq*4];
            sX[(kq*4+0)*64 + m] = xv.x;
            sX[(kq*4+1)*64 + m] = xv.y;
            sX[(kq*4+2)*64 + m] = xv.z;
            sX[(kq*4+3)*64 + m] = xv.w;
        }
        __syncthreads();
        #pragma unroll
        for (int k = 0; k < 16; k++){
            float4 xr = *(float4*)&sX[k*64 + ty*4];
            float xm[4] = {xr.x, xr.y, xr.z, xr.w};
            float4 w0 = *(float4*)&sW[k*192 + tx*12 + 0];
            float4 w1 = *(float4*)&sW[k*192 + tx*12 + 4];
            float4 w2 = *(float4*)&sW[k*192 + tx*12 + 8];
            float wv[12] = {w0.x,w0.y,w0.z,w0.w, w1.x,w1.y,w1.z,w1.w, w2.x,w2.y,w2.z,w2.w};
            #pragma unroll
            for (int mi = 0; mi < 4; mi++)
                #pragma unroll
                for (int nj = 0; nj < 12; nj++)
                    acc[mi][nj] = fmaf(xm[mi], wv[nj], acc[mi][nj]);
        }
        __syncthreads();
    }

    #pragma unroll
    for (int mi = 0; mi < 4; mi++){
        int m = mb + ty*4 + mi;
        #pragma unroll
        for (int nj = 0; nj < 12; nj++){
            int n = tx*12 + nj;
            float val = acc[mi][nj] + sB[n];
            if (n < 64){
                g_v[m*64 + n] = val;
            } else if (n < 128){
                g_k[m*64 + (n - 64)] = val;
            } else {
                float lsig = fminf(val, 0.0f) - log1pf(expf(-fabsf(val)));
                g_la[m*64 + (n - 128)] = fmaxf(lsig, LOG_EPS);
            }
        }
    }
}

// ---------------- K2: fused chunk sums + exclusive prefix (coalesced) ---------
__global__ void __launch_bounds__(1024) la_scan(){
    __shared__ float tile[32][33];
    int lane = threadIdx.x & 31;
    int wid  = threadIdx.x >> 5;          // 0..31
    int bnBase = blockIdx.x * 32;
    int myBn = bnBase + wid;
    float carry = 0.0f;
    #pragma unroll
    for (int pass = 0; pass < NCH/32; pass++){
        int c = pass*32 + wid;
        const float* p = g_la + c*TCHK*512 + bnBase + lane;
        float s = 0.0f;
        #pragma unroll
        for (int i = 0; i < TCHK; i++) s += p[i*512];
        tile[wid][lane] = s;
        __syncthreads();
        float v = tile[lane][wid];
        float sc = v;
        #pragma unroll
        for (int off = 1; off < 32; off <<= 1){
            float t = __shfl_up_sync(0xffffffffu, sc, off);
            if (lane >= off) sc += t;
        }
        float ex = __shfl_up_sync(0xffffffffu, sc, 1);
        if (lane == 0) ex = 0.0f;
        float tot = __shfl_sync(0xffffffffu, sc, 31);
        __syncthreads();
        tile[lane][wid] = carry + ex;
        carry += tot;
        __syncthreads();
        g_carry[(pass*32 + wid)*512 + bnBase + lane] = tile[wid][lane];
        __syncthreads();
    }
    if (lane == 31) g_inv[myBn] = 1.0f / (expf(carry) + 1e-8f);
}

// ---------------- shared fill: v tile + computed kd tile ----------------------
// s_v[t*64+d] from g_v; s_kd[t*64+n] computed from k, la, carry, inv.
// Thread map for kd: n = tid&63 (coalesced), cl = tid>>6 (chunk-in-seg 0..3).
__device__ __forceinline__ void fill_tiles(float* s_v, float* s_kd, int seg, int b, int tid){
    // v tile: 32t x 64d = 512 float4, 2 per thread
    #pragma unroll
    for (int i = tid; i < SEGT*16; i += 256){
        int t = i >> 4, q = i & 15;
        int row = ((seg*SEGT + t)*B_DIM + b)*64;
        ((float4*)s_v)[i] = *(const float4*)&g_v[row + q*4];
    }
    // kd tile: compute decay on the fly (identical ops/order to old decay_fold)
    {
        int n  = tid & 63;
        int cl = tid >> 6;               // 0..3
        int c  = seg*4 + cl;             // global chunk
        int bn = b*64 + n;
        float cum = g_carry[c*512 + bn];
        float inv = g_inv[bn];
        #pragma unroll
        for (int i = 0; i < TCHK; i++){
            int t = cl*TCHK + i;
            int addr = ((seg*SEGT + t)*B_DIM + b)*64 + n;
            cum += g_la[addr];
            float dec = expf(cum) * inv;
            s_kd[t*64 + n] = g_k[addr] * dec;
        }
    }
    __syncthreads();
}

// ---------------- K4: per-segment outer-product sums ----------
__global__ void __launch_bounds__(256) seg_sums(){
    int seg = blockIdx.x, b = blockIdx.y;
    __shared__ float s_v[SEGT*64];
    __shared__ float s_kd[SEGT*64];
    int tid = threadIdx.x;
    fill_tiles(s_v, s_kd, seg, b, tid);
    int dq = tid >> 4, n4 = tid & 15;
    float4 a0 = {0,0,0,0}, a1 = {0,0,0,0}, a2 = {0,0,0,0}, a3 = {0,0,0,0};
    #pragma unroll 4
    for (int t = 0; t < SEGT; t++){
        float4 kd = *(const float4*)&s_kd[t*64 + n4*4];
        float4 vv = *(const float4*)&s_v [t*64 + dq*4];
        a0.x = fmaf(vv.x, kd.x, a0.x); a0.y = fmaf(vv.x, kd.y, a0.y);
        a0.z = fmaf(vv.x, kd.z, a0.z); a0.w = fmaf(vv.x, kd.w, a0.w);
        a1.x = fmaf(vv.y, kd.x, a1.x); a1.y = fmaf(vv.y, kd.y, a1.y);
        a1.z = fmaf(vv.y, kd.z, a1.z); a1.w = fmaf(vv.y, kd.w, a1.w);
        a2.x = fmaf(vv.z, kd.x, a2.x); a2.y = fmaf(vv.z, kd.y, a2.y);
        a2.z = fmaf(vv.z, kd.z, a2.z); a2.w = fmaf(vv.z, kd.w, a2.w);
        a3.x = fmaf(vv.w, kd.x, a3.x); a3.y = fmaf(vv.w, kd.y, a3.y);
        a3.z = fmaf(vv.w, kd.z, a3.z); a3.w = fmaf(vv.w, kd.w, a3.w);
    }
    float* P = g_P + (seg*B_DIM + b)*4096;
    *(float4*)&P[(dq*4+0)*64 + n4*4] = a0;
    *(float4*)&P[(dq*4+1)*64 + n4*4] = a1;
    *(float4*)&P[(dq*4+2)*64 + n4*4] = a2;
    *(float4*)&P[(dq*4+3)*64 + n4*4] = a3;
}

// ---------------- K4b: in-place exclusive prefix of P along seg ---------------
__global__ void __launch_bounds__(256) seg_prefix(){
    int idx = blockIdx.x*256 + threadIdx.x;   // 0..32767
    float carry = 0.0f;
    #pragma unroll 8
    for (int s = 0; s < NSEG; s++){
        float v = g_P[s*32768 + idx];
        g_P[s*32768 + idx] = carry;
        carry += v;
    }
}

// ---------------- K5: scan + store (128 MB) ---------------------
__global__ void __launch_bounds__(256) scan_kernel(float* __restrict__ out){
    int seg = blockIdx.x, b = blockIdx.y;
    __shared__ float s_v[SEGT*64];
    __shared__ float s_kd[SEGT*64];
    int tid = threadIdx.x;
    fill_tiles(s_v, s_kd, seg, b, tid);
    int dq = tid >> 4, n4 = tid & 15;
    const float* P = g_P + (seg*B_DIM + b)*4096;
    float4 a0 = *(const float4*)&P[(dq*4+0)*64 + n4*4];
    float4 a1 = *(const float4*)&P[(dq*4+1)*64 + n4*4];
    float4 a2 = *(const float4*)&P[(dq*4+2)*64 + n4*4];
    float4 a3 = *(const float4*)&P[(dq*4+3)*64 + n4*4];
    #pragma unroll 4
    for (int t = 0; t < SEGT; t++){
        float4 kd = *(const float4*)&s_kd[t*64 + n4*4];
        float4 vv = *(const float4*)&s_v [t*64 + dq*4];
        a0.x = fmaf(vv.x, kd.x, a0.x); a0.y = fmaf(vv.x, kd.y, a0.y);
        a0.z = fmaf(vv.x, kd.z, a0.z); a0.w = fmaf(vv.x, kd.w, a0.w);
        a1.x = fmaf(vv.y, kd.x, a1.x); a1.y = fmaf(vv.y, kd.y, a1.y);
        a1.z = fmaf(vv.y, kd.z, a1.z); a1.w = fmaf(vv.y, kd.w, a1.w);
        a2.x = fmaf(vv.z, kd.x, a2.x); a2.y = fmaf(vv.z, kd.y, a2.y);
        a2.z = fmaf(vv.z, kd.z, a2.z); a2.w = fmaf(vv.z, kd.w, a2.w);
        a3.x = fmaf(vv.w, kd.x, a3.x); a3.y = fmaf(vv.w, kd.y, a3.y);
        a3.z = fmaf(vv.w, kd.z, a3.z); a3.w = fmaf(vv.w, kd.w, a3.w);
        float* orow = out + (size_t)((seg*SEGT + t)*B_DIM + b)*4096;
        *(float4*)&orow[(dq*4+0)*64 + n4*4] = a0;
        *(float4*)&orow[(dq*4+1)*64 + n4*4] = a1;
        *(float4*)&orow[(dq*4+2)*64 + n4*4] = a2;
        *(float4*)&orow[(dq*4+3)*64 + n4*4] = a3;
    }
}

// ---------------- launch ----------------
extern "C" void kernel_launch(void* const* d_in, const int* in_sizes, int n_in,
                              void* d_out, int out_size){
    const float* x  = (const float*)d_in[0];
    const float* Wv = (const float*)d_in[1];
    const float* bv = (const float*)d_in[2];
    const float* Wk = (const float*)d_in[3];
    const float* bk = (const float*)d_in[4];
    const float* Wa = (const float*)d_in[5];
    const float* ba = (const float*)d_in[6];
    float* out = (float*)d_out;

    pack_weights<<<(NOUT*INDIM + 255)/256, 256>>>(Wv, bv, Wk, bk, Wa, ba);
    proj_kernel<<<M_TOT/64, 256>>>(x);
    la_scan<<<16, 1024>>>();
    dim3 gseg(NSEG, B_DIM);
    seg_sums<<<gseg, 256>>>();
    seg_prefix<<<128, 256>>>();
    scan_kernel<<<gseg, 256>>>(out);
}

// round 14
// speedup vs baseline: 2.1317x; 1.3381x over previous
#include <cuda_runtime.h>
#include <cuda_bf16.h>
#include <math.h>
#include <cstdint>

// Problem constants
#define T_DIM   1024
#define B_DIM   8
#define INDIM   512
#define M_TOT   (T_DIM*B_DIM)   // 8192 rows (t,b)
#define NCH     128          // chunks for log-cumsum (chunk = 8 t)
#define TCHK    8            // t per chunk
#define NSEG    32           // segments for the S scan
#define SEGT    32           // t per segment (= 4 chunks)
#define NOUT    192

#define LOG_EPS (-18.420680743952367f)   // logf(1e-8f)

// ---------------- device scratch (no allocations allowed) ----------------
__device__ float g_v [M_TOT*64];       // (t*8+b)*64 + d
__device__ float g_k [M_TOT*64];
__device__ float g_la[M_TOT*64];       // log(max(sigmoid(a),eps))
__device__ float g_carry[NCH*512];     // exclusive prefix of chunk sums
__device__ float g_inv[512];           // 1/(exp(total)+1e-8)
__device__ float g_P[NSEG*B_DIM*64*64];  // segment sums -> exclusive prefix (4 MB)

// ---------------- helpers ----------------
__device__ __forceinline__ uint32_t cvt_bf16x2(float lo, float hi){
    uint32_t r;
    asm("cvt.rn.satfinite.bf16x2.f32 %0, %1, %2;" : "=r"(r) : "f"(hi), "f"(lo));
    return r;   // low 16 bits = lo
}
// m16n8k16 row.col bf16 MMA, fp32 accum (sm_80+, works on bare sm_103)
__device__ __forceinline__ void mma16816(float* c, const uint32_t* a, uint32_t b0, uint32_t b1){
    asm volatile(
        "mma.sync.aligned.m16n8k16.row.col.f32.bf16.bf16.f32 "
        "{%0,%1,%2,%3}, {%4,%5,%6,%7}, {%8,%9}, {%0,%1,%2,%3};"
        : "+f"(c[0]), "+f"(c[1]), "+f"(c[2]), "+f"(c[3])
        : "r"(a[0]), "r"(a[1]), "r"(a[2]), "r"(a[3]), "r"(b0), "r"(b1));
}

// ---------------- K1: mma.sync bf16-split projection GEMM ---------------------
// C[8192,192] = X[8192,512] @ W^T via Xh*Wh + Xh*Wl + Xl*Wh (fp32 accum).
// 64 CTAs x 256 threads; warp w owns rows w*16..w*16+15, all 192 cols.
#define KC   64
#define NCHK (INDIM/KC)     // 8
#define SA   72             // bf16 row stride (36 words == 4 mod 32: conflict-free frags)
#define OFF_AH   0
#define OFF_AL   18432      // 128*72*2
#define OFF_BH   36864
#define OFF_BL   64512      // +192*72*2
#define OFF_BIAS 92160
#define SMEM_PROJ (92160 + 192*4)

__global__ void __launch_bounds__(256) proj_mma(
    const float* __restrict__ x,
    const float* __restrict__ Wv, const float* __restrict__ bv,
    const float* __restrict__ Wk, const float* __restrict__ bk,
    const float* __restrict__ Wa, const float* __restrict__ ba)
{
    extern __shared__ char smem[];
    uint16_t* sAH = (uint16_t*)(smem + OFF_AH);
    uint16_t* sAL = (uint16_t*)(smem + OFF_AL);
    uint16_t* sBH = (uint16_t*)(smem + OFF_BH);
    uint16_t* sBL = (uint16_t*)(smem + OFF_BL);
    float*  sBias = (float*)(smem + OFF_BIAS);

    int tid = threadIdx.x;
    int wid = tid >> 5, lid = tid & 31;
    int g = lid >> 2, t = lid & 3;
    int mb = blockIdx.x * 128;
    if (tid < NOUT)
        sBias[tid] = (tid < 64) ? bv[tid] : ((tid < 128) ? bk[tid-64] : ba[tid-128]);

    float c[24][4];
    #pragma unroll
    for (int j = 0; j < 24; j++)
        #pragma unroll
        for (int q = 0; q < 4; q++) c[j][q] = 0.0f;

    for (int ch = 0; ch < NCHK; ch++){
        int kk = ch * KC;
        // ---- A fill: 128 rows x 16 float4 (8 iters/thread) ----
        #pragma unroll
        for (int it = 0; it < 8; it++){
            int i = tid + it*256;
            int row = i >> 4, q = i & 15;
            float4 xv = *(const float4*)&x[(mb + row)*INDIM + kk + q*4];
            uint32_t h01 = cvt_bf16x2(xv.x, xv.y);
            uint32_t h23 = cvt_bf16x2(xv.z, xv.w);
            float f0 = __uint_as_float(h01 << 16);
            float f1 = __uint_as_float(h01 & 0xFFFF0000u);
            float f2 = __uint_as_float(h23 << 16);
            float f3 = __uint_as_float(h23 & 0xFFFF0000u);
            uint32_t l01 = cvt_bf16x2(xv.x - f0, xv.y - f1);
            uint32_t l23 = cvt_bf16x2(xv.z - f2, xv.w - f3);
            int off = row*SA + q*4;
            *(uint2*)&sAH[off] = make_uint2(h01, h23);
            *(uint2*)&sAL[off] = make_uint2(l01, l23);
        }
        // ---- B fill: 192 rows x 16 float4 (12 iters/thread) ----
        #pragma unroll
        for (int it = 0; it < 12; it++){
            int i = tid + it*256;
            int row = i >> 4, q = i & 15;
            const float* W = (row < 64) ? &Wv[row*INDIM] :
                             (row < 128) ? &Wk[(row-64)*INDIM] : &Wa[(row-128)*INDIM];
            float4 wv = *(const float4*)&W[kk + q*4];
            uint32_t h01 = cvt_bf16x2(wv.x, wv.y);
            uint32_t h23 = cvt_bf16x2(wv.z, wv.w);
            float f0 = __uint_as_float(h01 << 16);
            float f1 = __uint_as_float(h01 & 0xFFFF0000u);
            float f2 = __uint_as_float(h23 << 16);
            float f3 = __uint_as_float(h23 & 0xFFFF0000u);
            uint32_t l01 = cvt_bf16x2(wv.x - f0, wv.y - f1);
            uint32_t l23 = cvt_bf16x2(wv.z - f2, wv.w - f3);
            int off = row*SA + q*4;
            *(uint2*)&sBH[off] = make_uint2(h01, h23);
            *(uint2*)&sBL[off] = make_uint2(l01, l23);
        }
        __syncthreads();
        // ---- MMA: 4 K=16 steps, 24 n-tiles, 3 split products each ----
        #pragma unroll
        for (int ks = 0; ks < 4; ks++){
            int ak = ks*16;
            int ra = (wid*16 + g)*SA + ak + 2*t;
            uint32_t aH[4], aL[4];
            aH[0] = *(const uint32_t*)&sAH[ra];
            aH[1] = *(const uint32_t*)&sAH[ra + 8*SA];
            aH[2] = *(const uint32_t*)&sAH[ra + 8];
            aH[3] = *(const uint32_t*)&sAH[ra + 8*SA + 8];
            aL[0] = *(const uint32_t*)&sAL[ra];
            aL[1] = *(const uint32_t*)&sAL[ra + 8*SA];
            aL[2] = *(const uint32_t*)&sAL[ra + 8];
            aL[3] = *(const uint32_t*)&sAL[ra + 8*SA + 8];
            #pragma unroll
            for (int j = 0; j < 24; j++){
                int rb = (j*8 + g)*SA + ak + 2*t;
                uint32_t bH0 = *(const uint32_t*)&sBH[rb];
                uint32_t bH1 = *(const uint32_t*)&sBH[rb + 8];
                uint32_t bL0 = *(const uint32_t*)&sBL[rb];
                uint32_t bL1 = *(const uint32_t*)&sBL[rb + 8];
                mma16816(c[j], aH, bH0, bH1);
                mma16816(c[j], aH, bL0, bL1);
                mma16816(c[j], aL, bH0, bH1);
            }
        }
        __syncthreads();
    }

    // ---- epilogue: bias + routing; c[j] covers rows (row0,row0+8), cols j*8+2t..+1
    int row0 = mb + wid*16 + g;
    #pragma unroll
    for (int j = 0; j < 24; j++){
        float b0 = sBias[j*8 + 2*t];
        float b1 = sBias[j*8 + 2*t + 1];
        float v00 = c[j][0] + b0, v01 = c[j][1] + b1;    // row0
        float v10 = c[j][2] + b0, v11 = c[j][3] + b1;    // row0+8
        int col = (j & 7)*8 + 2*t;
        if (j < 8){
            *(float2*)&g_v[row0*64 + col]     = make_float2(v00, v01);
            *(float2*)&g_v[(row0+8)*64 + col] = make_float2(v10, v11);
        } else if (j < 16){
            *(float2*)&g_k[row0*64 + col]     = make_float2(v00, v01);
            *(float2*)&g_k[(row0+8)*64 + col] = make_float2(v10, v11);
        } else {
            float s00 = fmaxf(fminf(v00,0.0f) - log1pf(expf(-fabsf(v00))), LOG_EPS);
            float s01 = fmaxf(fminf(v01,0.0f) - log1pf(expf(-fabsf(v01))), LOG_EPS);
            float s10 = fmaxf(fminf(v10,0.0f) - log1pf(expf(-fabsf(v10))), LOG_EPS);
            float s11 = fmaxf(fminf(v11,0.0f) - log1pf(expf(-fabsf(v11))), LOG_EPS);
            *(float2*)&g_la[row0*64 + col]     = make_float2(s00, s01);
            *(float2*)&g_la[(row0+8)*64 + col] = make_float2(s10, s11);
        }
    }
}

// ---------------- K2: fused chunk sums + exclusive prefix (coalesced) ---------
__global__ void __launch_bounds__(1024) la_scan(){
    __shared__ float tile[32][33];
    int lane = threadIdx.x & 31;
    int wid  = threadIdx.x >> 5;
    int bnBase = blockIdx.x * 32;
    int myBn = bnBase + wid;
    float carry = 0.0f;
    #pragma unroll
    for (int pass = 0; pass < NCH/32; pass++){
        int c = pass*32 + wid;
        const float* p = g_la + c*TCHK*512 + bnBase + lane;
        float s = 0.0f;
        #pragma unroll
        for (int i = 0; i < TCHK; i++) s += p[i*512];
        tile[wid][lane] = s;
        __syncthreads();
        float v = tile[lane][wid];
        float sc = v;
        #pragma unroll
        for (int off = 1; off < 32; off <<= 1){
            float t = __shfl_up_sync(0xffffffffu, sc, off);
            if (lane >= off) sc += t;
        }
        float ex = __shfl_up_sync(0xffffffffu, sc, 1);
        if (lane == 0) ex = 0.0f;
        float tot = __shfl_sync(0xffffffffu, sc, 31);
        __syncthreads();
        tile[lane][wid] = carry + ex;
        carry += tot;
        __syncthreads();
        g_carry[(pass*32 + wid)*512 + bnBase + lane] = tile[wid][lane];
        __syncthreads();
    }
    if (lane == 31) g_inv[myBn] = 1.0f / (expf(carry) + 1e-8f);
}

// ---------------- shared fill: v tile + computed kd tile ----------------------
__device__ __forceinline__ void fill_tiles(float* s_v, float* s_kd, int seg, int b, int tid){
    #pragma unroll
    for (int i = tid; i < SEGT*16; i += 256){
        int t = i >> 4, q = i & 15;
        int row = ((seg*SEGT + t)*B_DIM + b)*64;
        ((float4*)s_v)[i] = *(const float4*)&g_v[row + q*4];
    }
    {
        int n  = tid & 63;
        int cl = tid >> 6;
        int c  = seg*4 + cl;
        int bn = b*64 + n;
        float cum = g_carry[c*512 + bn];
        float inv = g_inv[bn];
        #pragma unroll
        for (int i = 0; i < TCHK; i++){
            int t = cl*TCHK + i;
            int addr = ((seg*SEGT + t)*B_DIM + b)*64 + n;
            cum += g_la[addr];
            float dec = expf(cum) * inv;
            s_kd[t*64 + n] = g_k[addr] * dec;
        }
    }
    __syncthreads();
}

// ---------------- K4: per-segment outer-product sums ----------
__global__ void __launch_bounds__(256) seg_sums(){
    int seg = blockIdx.x, b = blockIdx.y;
    __shared__ float s_v[SEGT*64];
    __shared__ float s_kd[SEGT*64];
    int tid = threadIdx.x;
    fill_tiles(s_v, s_kd, seg, b, tid);
    int dq = tid >> 4, n4 = tid & 15;
    float4 a0 = {0,0,0,0}, a1 = {0,0,0,0}, a2 = {0,0,0,0}, a3 = {0,0,0,0};
    #pragma unroll 4
    for (int t = 0; t < SEGT; t++){
        float4 kd = *(const float4*)&s_kd[t*64 + n4*4];
        float4 vv = *(const float4*)&s_v [t*64 + dq*4];
        a0.x = fmaf(vv.x, kd.x, a0.x); a0.y = fmaf(vv.x, kd.y, a0.y);
        a0.z = fmaf(vv.x, kd.z, a0.z); a0.w = fmaf(vv.x, kd.w, a0.w);
        a1.x = fmaf(vv.y, kd.x, a1.x); a1.y = fmaf(vv.y, kd.y, a1.y);
        a1.z = fmaf(vv.y, kd.z, a1.z); a1.w = fmaf(vv.y, kd.w, a1.w);
        a2.x = fmaf(vv.z, kd.x, a2.x); a2.y = fmaf(vv.z, kd.y, a2.y);
        a2.z = fmaf(vv.z, kd.z, a2.z); a2.w = fmaf(vv.z, kd.w, a2.w);
        a3.x = fmaf(vv.w, kd.x, a3.x); a3.y = fmaf(vv.w, kd.y, a3.y);
        a3.z = fmaf(vv.w, kd.z, a3.z); a3.w = fmaf(vv.w, kd.w, a3.w);
    }
    float* P = g_P + (seg*B_DIM + b)*4096;
    *(float4*)&P[(dq*4+0)*64 + n4*4] = a0;
    *(float4*)&P[(dq*4+1)*64 + n4*4] = a1;
    *(float4*)&P[(dq*4+2)*64 + n4*4] = a2;
    *(float4*)&P[(dq*4+3)*64 + n4*4] = a3;
}

// ---------------- K4b: in-place exclusive prefix of P along seg ---------------
__global__ void __launch_bounds__(256) seg_prefix(){
    int idx = blockIdx.x*256 + threadIdx.x;
    float carry = 0.0f;
    #pragma unroll 8
    for (int s = 0; s < NSEG; s++){
        float v = g_P[s*32768 + idx];
        g_P[s*32768 + idx] = carry;
        carry += v;
    }
}

// ---------------- K5: scan + store (128 MB) ---------------------
__global__ void __launch_bounds__(256) scan_kernel(float* __restrict__ out){
    int seg = blockIdx.x, b = blockIdx.y;
    __shared__ float s_v[SEGT*64];
    __shared__ float s_kd[SEGT*64];
    int tid = threadIdx.x;
    fill_tiles(s_v, s_kd, seg, b, tid);
    int dq = tid >> 4, n4 = tid & 15;
    const float* P = g_P + (seg*B_DIM + b)*4096;
    float4 a0 = *(const float4*)&P[(dq*4+0)*64 + n4*4];
    float4 a1 = *(const float4*)&P[(dq*4+1)*64 + n4*4];
    float4 a2 = *(const float4*)&P[(dq*4+2)*64 + n4*4];
    float4 a3 = *(const float4*)&P[(dq*4+3)*64 + n4*4];
    #pragma unroll 4
    for (int t = 0; t < SEGT; t++){
        float4 kd = *(const float4*)&s_kd[t*64 + n4*4];
        float4 vv = *(const float4*)&s_v [t*64 + dq*4];
        a0.x = fmaf(vv.x, kd.x, a0.x); a0.y = fmaf(vv.x, kd.y, a0.y);
        a0.z = fmaf(vv.x, kd.z, a0.z); a0.w = fmaf(vv.x, kd.w, a0.w);
        a1.x = fmaf(vv.y, kd.x, a1.x); a1.y = fmaf(vv.y, kd.y, a1.y);
        a1.z = fmaf(vv.y, kd.z, a1.z); a1.w = fmaf(vv.y, kd.w, a1.w);
        a2.x = fmaf(vv.z, kd.x, a2.x); a2.y = fmaf(vv.z, kd.y, a2.y);
        a2.z = fmaf(vv.z, kd.z, a2.z); a2.w = fmaf(vv.z, kd.w, a2.w);
        a3.x = fmaf(vv.w, kd.x, a3.x); a3.y = fmaf(vv.w, kd.y, a3.y);
        a3.z = fmaf(vv.w, kd.z, a3.z); a3.w = fmaf(vv.w, kd.w, a3.w);
        float* orow = out + (size_t)((seg*SEGT + t)*B_DIM + b)*4096;
        *(float4*)&orow[(dq*4+0)*64 + n4*4] = a0;
        *(float4*)&orow[(dq*4+1)*64 + n4*4] = a1;
        *(float4*)&orow[(dq*4+2)*64 + n4*4] = a2;
        *(float4*)&orow[(dq*4+3)*64 + n4*4] = a3;
    }
}

// ---------------- launch ----------------
extern "C" void kernel_launch(void* const* d_in, const int* in_sizes, int n_in,
                              void* d_out, int out_size){
    const float* x  = (const float*)d_in[0];
    const float* Wv = (const float*)d_in[1];
    const float* bv = (const float*)d_in[2];
    const float* Wk = (const float*)d_in[3];
    const float* bk = (const float*)d_in[4];
    const float* Wa = (const float*)d_in[5];
    const float* ba = (const float*)d_in[6];
    float* out = (float*)d_out;

    static int attr_set = 0;
    if (!attr_set){
        cudaFuncSetAttribute(proj_mma, cudaFuncAttributeMaxDynamicSharedMemorySize, SMEM_PROJ);
        attr_set = 1;
    }
    proj_mma<<<M_TOT/128, 256, SMEM_PROJ>>>(x, Wv, bv, Wk, bk, Wa, ba);
    la_scan<<<16, 1024>>>();
    dim3 gseg(NSEG, B_DIM);
    seg_sums<<<gseg, 256>>>();
    seg_prefix<<<128, 256>>>();
    scan_kernel<<<gseg, 256>>>(out);
}